// round 8
// baseline (speedup 1.0000x reference)
#include <cuda_runtime.h>

// LSTM_87067577025240 — Round 5: eliminate operand-duplication MOVs.
// R4 ncu: alu=34.6% — pack2(w,w) costs 8 MOVs/k. Fix: pair accumulators over
// GATES ({g,i},{f,o}) so FFMA2's 'a' operand is the natural low/high u64 of the
// float4 weight load (zero packing), and keep h PRE-DUPLICATED in smem so 'b'
// operands come straight from LDS.128 ({h_j,h_j,h_j+1,h_j+1}).
//   * per k: 1 LDG.128 + 7 LDS.128 + 28 FFMA2, no MOVs
//   * PF=4 register prefetch ring on weights (validated in R4)
//   * 147 CTAs (NB=14) on 148 SMs; c state in smem; exact-fp32 nonlinearities

#define SEQ   256
#define H     512
#define B_TOT 2048
#define C_OUT 10
#define NB    14                          // batch columns per CTA
#define ROW_U64 16                        // hs2 row stride in u64 (128B rows)
#define NCTA  ((B_TOT + NB - 1) / NB)     // 147
#define NPAIR (NB / 2)                    // 7 LDS.128 per k
#define PF    4                           // weight prefetch depth

typedef unsigned long long u64;

// Gate-fused transposed weights, padded by PF rows for the prefetch ring:
// g_Wt[k*H + t] = {wgh[t][k], wih[t][k], wfh[t][k], woh[t][k]}
// Loaded as ulonglong2: .x = {wg,wi}, .y = {wf,wo} — FFMA2 'a' operands as-is.
__device__ __align__(16) float4 g_Wt[(H + PF) * H];

__device__ __forceinline__ u64 pack2(float lo, float hi) {
    u64 r;
    asm("mov.b64 %0, {%1, %2};" : "=l"(r) : "f"(lo), "f"(hi));
    return r;
}
__device__ __forceinline__ void unpack2(u64 v, float &lo, float &hi) {
    asm("mov.b64 {%0, %1}, %2;" : "=f"(lo), "=f"(hi) : "l"(v));
}
__device__ __forceinline__ u64 fma2(u64 a, u64 b, u64 c) {
    u64 d;
    asm("fma.rn.f32x2 %0, %1, %2, %3;" : "=l"(d) : "l"(a), "l"(b), "l"(c));
    return d;
}

// sigmoid / tanh built on MUFU.EX2 (rel err ~2^-22); avoids tanh.approx (2^-11)
// whose error would compound over 256 recurrent steps. MUFU cost is ~2% — keep exact.
__device__ __forceinline__ float sigmoid_f(float x) {
    return 1.0f / (1.0f + __expf(-x));
}
__device__ __forceinline__ float tanh_f(float x) {
    float ax = fabsf(x);
    float e  = __expf(-2.0f * ax);
    float t  = (1.0f - e) / (1.0f + e);
    return copysignf(t, x);
}

__global__ void prepack_kernel(const float* __restrict__ wgh,
                               const float* __restrict__ wih,
                               const float* __restrict__ wfh,
                               const float* __restrict__ woh) {
    int id = blockIdx.x * blockDim.x + threadIdx.x;   // [0, H*H)
    int k  = id & (H - 1);
    int t  = id >> 9;
    g_Wt[k * H + t] = make_float4(wgh[t * H + k], wih[t * H + k],
                                  wfh[t * H + k], woh[t * H + k]);
}

__global__ __launch_bounds__(H, 1)
void lstm_kernel(const float* __restrict__ x,
                 const float* __restrict__ wgx, const float* __restrict__ wix,
                 const float* __restrict__ wfx, const float* __restrict__ wox,
                 const float* __restrict__ bg,  const float* __restrict__ bi,
                 const float* __restrict__ bf,  const float* __restrict__ bo,
                 const float* __restrict__ wph, const float* __restrict__ bp,
                 const float* __restrict__ h_init, const float* __restrict__ c_init,
                 float* __restrict__ out) {
    extern __shared__ __align__(16) char smem_raw[];
    u64*   hs2 = reinterpret_cast<u64*>(smem_raw);        // [H][ROW_U64]: hs2[k][j]={h,h}
    float* cs  = reinterpret_cast<float*>(hs2 + H * ROW_U64); // [H][NB] c state
    float* xs  = cs + H * NB;                              // [16] current x per column

    const int t    = threadIdx.x;        // h-row owned by this thread
    const int base = blockIdx.x * NB;    // first batch column of this CTA

    const float wgx_r = wgx[t], wix_r = wix[t], wfx_r = wfx[t], wox_r = wox[t];
    const float bg_r  = bg[t],  bi_r  = bi[t],  bf_r  = bf[t],  bo_r  = bo[t];

    const float h0 = h_init[t];
    const float c0 = c_init[t];
    const u64   h0d = pack2(h0, h0);
#pragma unroll
    for (int j = 0; j < ROW_U64; j++) hs2[t * ROW_U64 + j] = h0d;
#pragma unroll
    for (int j = 0; j < NB; j++)      cs[t * NB + j] = c0;
    if (t < 16) xs[t] = 0.0f;
    __syncthreads();

    const ulonglong2* __restrict__ Wt2 = reinterpret_cast<const ulonglong2*>(g_Wt);

    for (int s = 0; s < SEQ; s++) {
        if (t < NB) {
            const int b = base + t;
            xs[t] = (b < B_TOT) ? x[b * SEQ + s] : 0.0f;
        }

        // acc_gi[j] = {gate_g_acc_j, gate_i_acc_j}, acc_fo[j] = {f, o}
        u64 acc_gi[NB], acc_fo[NB];
#pragma unroll
        for (int j = 0; j < NB; j++) { acc_gi[j] = 0ULL; acc_fo[j] = 0ULL; }

        // prime the prefetch ring: PF weight rows in flight at all times
        ulonglong2 wbuf[PF];
#pragma unroll
        for (int i = 0; i < PF; i++) wbuf[i] = Wt2[i * H + t];

#pragma unroll 1
        for (int kg = 0; kg < H; kg += PF) {
#pragma unroll
            for (int i = 0; i < PF; i++) {
                const int k = kg + i;
                const ulonglong2 w = wbuf[i];         // .x={wg,wi}, .y={wf,wo}
                wbuf[i] = Wt2[(k + PF) * H + t];      // over-reads land in pad rows
                const ulonglong2* hrow = reinterpret_cast<const ulonglong2*>(&hs2[k * ROW_U64]);
#pragma unroll
                for (int jp = 0; jp < NPAIR; jp++) {
                    const ulonglong2 b2 = hrow[jp];   // LDS.128: {h_j,h_j},{h_j+1,h_j+1}
                    acc_gi[2*jp]   = fma2(w.x, b2.x, acc_gi[2*jp]);
                    acc_fo[2*jp]   = fma2(w.y, b2.x, acc_fo[2*jp]);
                    acc_gi[2*jp+1] = fma2(w.x, b2.y, acc_gi[2*jp+1]);
                    acc_fo[2*jp+1] = fma2(w.y, b2.y, acc_fo[2*jp+1]);
                }
            }
        }
        __syncthreads();   // everyone done reading hs2 before we overwrite it

        // elementwise: gates -> (c, h) update for this thread's row
#pragma unroll
        for (int j = 0; j < NB; j++) {
            float pg, pi, pf, po;
            unpack2(acc_gi[j], pg, pi);
            unpack2(acc_fo[j], pf, po);
            const float xv = xs[j];
            const float g = tanh_f   (pg + wgx_r * xv + bg_r);
            const float i = sigmoid_f(pi + wix_r * xv + bi_r);
            const float f = sigmoid_f(pf + wfx_r * xv + bf_r);
            const float o = sigmoid_f(po + wox_r * xv + bo_r);
            float c = cs[t * NB + j];
            c = g * i + c * f;
            cs[t * NB + j] = c;
            const float h = tanh_f(c) * o;
            hs2[t * ROW_U64 + j] = pack2(h, h);       // store pre-duplicated
        }
        __syncthreads();   // hs2(t+1) complete before next step's k-loop / xs write
    }

    // final projection: out[b][c] = wph[c][:] . h[:, b] + bp[c]
    if (t < NB * C_OUT) {
        const int j = t / C_OUT;
        const int c = t - j * C_OUT;
        const int b = base + j;
        if (b < B_TOT) {
            const float* hsf = reinterpret_cast<const float*>(hs2);
            float acc = bp[c];
#pragma unroll 8
            for (int k = 0; k < H; k++)
                acc += wph[c * H + k] * hsf[(k * ROW_U64 + j) * 2];  // lo of {h,h}
            out[b * C_OUT + c] = acc;
        }
    }
}

extern "C" void kernel_launch(void* const* d_in, const int* in_sizes, int n_in,
                              void* d_out, int out_size) {
    const float* x      = (const float*)d_in[0];
    const float* wgx    = (const float*)d_in[1];
    const float* wix    = (const float*)d_in[2];
    const float* wfx    = (const float*)d_in[3];
    const float* wox    = (const float*)d_in[4];
    const float* wgh    = (const float*)d_in[5];
    const float* wih    = (const float*)d_in[6];
    const float* wfh    = (const float*)d_in[7];
    const float* woh    = (const float*)d_in[8];
    const float* bg     = (const float*)d_in[9];
    const float* bi     = (const float*)d_in[10];
    const float* bf     = (const float*)d_in[11];
    const float* bo     = (const float*)d_in[12];
    const float* wph    = (const float*)d_in[13];
    const float* bp     = (const float*)d_in[14];
    const float* h_init = (const float*)d_in[15];
    const float* c_init = (const float*)d_in[16];
    float* out = (float*)d_out;

    const int smem_bytes = H * ROW_U64 * 8 + H * NB * 4 + 16 * 4;  // 32KB + 28KB + 64B
    cudaFuncSetAttribute(lstm_kernel, cudaFuncAttributeMaxDynamicSharedMemorySize, smem_bytes);

    prepack_kernel<<<(H * H) / 256, 256>>>(wgh, wih, wfh, woh);
    lstm_kernel<<<NCTA, H, smem_bytes>>>(x, wgx, wix, wfx, wox, bg, bi, bf, bo,
                                         wph, bp, h_init, c_init, out);
}

// round 9
// speedup vs baseline: 1.0015x; 1.0015x over previous
#include <cuda_runtime.h>

// LSTM_87067577025240 — Round 5: eliminate operand-duplication MOVs.
// R4 ncu: alu=34.6% — pack2(w,w) costs 8 MOVs/k. Fix: pair accumulators over
// GATES ({g,i},{f,o}) so FFMA2's 'a' operand is the natural low/high u64 of the
// float4 weight load (zero packing), and keep h PRE-DUPLICATED in smem so 'b'
// operands come straight from LDS.128 ({h_j,h_j,h_j+1,h_j+1}).
//   * per k: 1 LDG.128 + 7 LDS.128 + 28 FFMA2, no MOVs
//   * PF=4 register prefetch ring on weights (validated in R4)
//   * 147 CTAs (NB=14) on 148 SMs; c state in smem; exact-fp32 nonlinearities

#define SEQ   256
#define H     512
#define B_TOT 2048
#define C_OUT 10
#define NB    14                          // batch columns per CTA
#define ROW_U64 16                        // hs2 row stride in u64 (128B rows)
#define NCTA  ((B_TOT + NB - 1) / NB)     // 147
#define NPAIR (NB / 2)                    // 7 LDS.128 per k
#define PF    4                           // weight prefetch depth

typedef unsigned long long u64;

// Gate-fused transposed weights, padded by PF rows for the prefetch ring:
// g_Wt[k*H + t] = {wgh[t][k], wih[t][k], wfh[t][k], woh[t][k]}
// Loaded as ulonglong2: .x = {wg,wi}, .y = {wf,wo} — FFMA2 'a' operands as-is.
__device__ __align__(16) float4 g_Wt[(H + PF) * H];

__device__ __forceinline__ u64 pack2(float lo, float hi) {
    u64 r;
    asm("mov.b64 %0, {%1, %2};" : "=l"(r) : "f"(lo), "f"(hi));
    return r;
}
__device__ __forceinline__ void unpack2(u64 v, float &lo, float &hi) {
    asm("mov.b64 {%0, %1}, %2;" : "=f"(lo), "=f"(hi) : "l"(v));
}
__device__ __forceinline__ u64 fma2(u64 a, u64 b, u64 c) {
    u64 d;
    asm("fma.rn.f32x2 %0, %1, %2, %3;" : "=l"(d) : "l"(a), "l"(b), "l"(c));
    return d;
}

// sigmoid / tanh built on MUFU.EX2 (rel err ~2^-22); avoids tanh.approx (2^-11)
// whose error would compound over 256 recurrent steps. MUFU cost is ~2% — keep exact.
__device__ __forceinline__ float sigmoid_f(float x) {
    return 1.0f / (1.0f + __expf(-x));
}
__device__ __forceinline__ float tanh_f(float x) {
    float ax = fabsf(x);
    float e  = __expf(-2.0f * ax);
    float t  = (1.0f - e) / (1.0f + e);
    return copysignf(t, x);
}

__global__ void prepack_kernel(const float* __restrict__ wgh,
                               const float* __restrict__ wih,
                               const float* __restrict__ wfh,
                               const float* __restrict__ woh) {
    int id = blockIdx.x * blockDim.x + threadIdx.x;   // [0, H*H)
    int k  = id & (H - 1);
    int t  = id >> 9;
    g_Wt[k * H + t] = make_float4(wgh[t * H + k], wih[t * H + k],
                                  wfh[t * H + k], woh[t * H + k]);
}

__global__ __launch_bounds__(H, 1)
void lstm_kernel(const float* __restrict__ x,
                 const float* __restrict__ wgx, const float* __restrict__ wix,
                 const float* __restrict__ wfx, const float* __restrict__ wox,
                 const float* __restrict__ bg,  const float* __restrict__ bi,
                 const float* __restrict__ bf,  const float* __restrict__ bo,
                 const float* __restrict__ wph, const float* __restrict__ bp,
                 const float* __restrict__ h_init, const float* __restrict__ c_init,
                 float* __restrict__ out) {
    extern __shared__ __align__(16) char smem_raw[];
    u64*   hs2 = reinterpret_cast<u64*>(smem_raw);        // [H][ROW_U64]: hs2[k][j]={h,h}
    float* cs  = reinterpret_cast<float*>(hs2 + H * ROW_U64); // [H][NB] c state
    float* xs  = cs + H * NB;                              // [16] current x per column

    const int t    = threadIdx.x;        // h-row owned by this thread
    const int base = blockIdx.x * NB;    // first batch column of this CTA

    const float wgx_r = wgx[t], wix_r = wix[t], wfx_r = wfx[t], wox_r = wox[t];
    const float bg_r  = bg[t],  bi_r  = bi[t],  bf_r  = bf[t],  bo_r  = bo[t];

    const float h0 = h_init[t];
    const float c0 = c_init[t];
    const u64   h0d = pack2(h0, h0);
#pragma unroll
    for (int j = 0; j < ROW_U64; j++) hs2[t * ROW_U64 + j] = h0d;
#pragma unroll
    for (int j = 0; j < NB; j++)      cs[t * NB + j] = c0;
    if (t < 16) xs[t] = 0.0f;
    __syncthreads();

    const ulonglong2* __restrict__ Wt2 = reinterpret_cast<const ulonglong2*>(g_Wt);

    for (int s = 0; s < SEQ; s++) {
        if (t < NB) {
            const int b = base + t;
            xs[t] = (b < B_TOT) ? x[b * SEQ + s] : 0.0f;
        }

        // acc_gi[j] = {gate_g_acc_j, gate_i_acc_j}, acc_fo[j] = {f, o}
        u64 acc_gi[NB], acc_fo[NB];
#pragma unroll
        for (int j = 0; j < NB; j++) { acc_gi[j] = 0ULL; acc_fo[j] = 0ULL; }

        // prime the prefetch ring: PF weight rows in flight at all times
        ulonglong2 wbuf[PF];
#pragma unroll
        for (int i = 0; i < PF; i++) wbuf[i] = Wt2[i * H + t];

#pragma unroll 1
        for (int kg = 0; kg < H; kg += PF) {
#pragma unroll
            for (int i = 0; i < PF; i++) {
                const int k = kg + i;
                const ulonglong2 w = wbuf[i];         // .x={wg,wi}, .y={wf,wo}
                wbuf[i] = Wt2[(k + PF) * H + t];      // over-reads land in pad rows
                const ulonglong2* hrow = reinterpret_cast<const ulonglong2*>(&hs2[k * ROW_U64]);
#pragma unroll
                for (int jp = 0; jp < NPAIR; jp++) {
                    const ulonglong2 b2 = hrow[jp];   // LDS.128: {h_j,h_j},{h_j+1,h_j+1}
                    acc_gi[2*jp]   = fma2(w.x, b2.x, acc_gi[2*jp]);
                    acc_fo[2*jp]   = fma2(w.y, b2.x, acc_fo[2*jp]);
                    acc_gi[2*jp+1] = fma2(w.x, b2.y, acc_gi[2*jp+1]);
                    acc_fo[2*jp+1] = fma2(w.y, b2.y, acc_fo[2*jp+1]);
                }
            }
        }
        __syncthreads();   // everyone done reading hs2 before we overwrite it

        // elementwise: gates -> (c, h) update for this thread's row
#pragma unroll
        for (int j = 0; j < NB; j++) {
            float pg, pi, pf, po;
            unpack2(acc_gi[j], pg, pi);
            unpack2(acc_fo[j], pf, po);
            const float xv = xs[j];
            const float g = tanh_f   (pg + wgx_r * xv + bg_r);
            const float i = sigmoid_f(pi + wix_r * xv + bi_r);
            const float f = sigmoid_f(pf + wfx_r * xv + bf_r);
            const float o = sigmoid_f(po + wox_r * xv + bo_r);
            float c = cs[t * NB + j];
            c = g * i + c * f;
            cs[t * NB + j] = c;
            const float h = tanh_f(c) * o;
            hs2[t * ROW_U64 + j] = pack2(h, h);       // store pre-duplicated
        }
        __syncthreads();   // hs2(t+1) complete before next step's k-loop / xs write
    }

    // final projection: out[b][c] = wph[c][:] . h[:, b] + bp[c]
    if (t < NB * C_OUT) {
        const int j = t / C_OUT;
        const int c = t - j * C_OUT;
        const int b = base + j;
        if (b < B_TOT) {
            const float* hsf = reinterpret_cast<const float*>(hs2);
            float acc = bp[c];
#pragma unroll 8
            for (int k = 0; k < H; k++)
                acc += wph[c * H + k] * hsf[(k * ROW_U64 + j) * 2];  // lo of {h,h}
            out[b * C_OUT + c] = acc;
        }
    }
}

extern "C" void kernel_launch(void* const* d_in, const int* in_sizes, int n_in,
                              void* d_out, int out_size) {
    const float* x      = (const float*)d_in[0];
    const float* wgx    = (const float*)d_in[1];
    const float* wix    = (const float*)d_in[2];
    const float* wfx    = (const float*)d_in[3];
    const float* wox    = (const float*)d_in[4];
    const float* wgh    = (const float*)d_in[5];
    const float* wih    = (const float*)d_in[6];
    const float* wfh    = (const float*)d_in[7];
    const float* woh    = (const float*)d_in[8];
    const float* bg     = (const float*)d_in[9];
    const float* bi     = (const float*)d_in[10];
    const float* bf     = (const float*)d_in[11];
    const float* bo     = (const float*)d_in[12];
    const float* wph    = (const float*)d_in[13];
    const float* bp     = (const float*)d_in[14];
    const float* h_init = (const float*)d_in[15];
    const float* c_init = (const float*)d_in[16];
    float* out = (float*)d_out;

    const int smem_bytes = H * ROW_U64 * 8 + H * NB * 4 + 16 * 4;  // 32KB + 28KB + 64B
    cudaFuncSetAttribute(lstm_kernel, cudaFuncAttributeMaxDynamicSharedMemorySize, smem_bytes);

    prepack_kernel<<<(H * H) / 256, 256>>>(wgh, wih, wfh, woh);
    lstm_kernel<<<NCTA, H, smem_bytes>>>(x, wgx, wix, wfx, wox, bg, bi, bf, bo,
                                         wph, bp, h_init, c_init, out);
}